// round 9
// baseline (speedup 1.0000x reference)
#include <cuda_runtime.h>
#include <cuda_bf16.h>
#include <cuda_fp16.h>
#include <stdint.h>
#include <math.h>

#define BQ 2
#define TQ 2048
#define CQ 1024
#define HQ 16
#define DQ 64
#define BH (BQ*HQ)
#define M_ROWS (BQ*TQ)          // 4096
#define K3 3072                 // tripled K for hi/lo split GEMM

// GEMM smem geometry (dynamic): 3 stages
#define GA_ELE (128*40)         // As stage elems
#define GB_ELE (32*136)         // Bs stage elems
#define GEMM_SMEM_BYTES (3 * (GA_ELE + GB_ELE) * 2)   // 56832

// Scratch (allocation-free rule: static device globals)
__device__ float g_q[BQ*HQ*TQ*DQ];
__device__ float g_k[BQ*HQ*TQ*DQ];
__device__ float g_v[BQ*HQ*TQ*DQ];
__device__ __half g_qh[BQ*HQ*TQ*DQ];    // fp16 q, pre-scaled by 1/8
__device__ __half g_kh[BQ*HQ*TQ*DQ];    // fp16 k ([bh][t][d])
__device__ __half g_vh[BQ*HQ*TQ*DQ];    // fp16 v
__device__ __nv_bfloat16 g_A3[(long)M_ROWS * K3];     // [4096, 3072]
__device__ __nv_bfloat16 g_B3[(long)K3 * 3072];       // qkv weights split
__device__ __nv_bfloat16 g_B3p[(long)K3 * 1024];      // proj weights split

// ---------------------------------------------------------------------------
// fp32 -> (hi, lo) bf16 split conversions.
// ---------------------------------------------------------------------------
__global__ void conv_A3(const float* __restrict__ src)
{
    int i = blockIdx.x * blockDim.x + threadIdx.x;
    if (i >= M_ROWS * CQ) return;
    int m = i >> 10, k = i & 1023;
    float v = src[i];
    __nv_bfloat16 hi = __float2bfloat16(v);
    __nv_bfloat16 lo = __float2bfloat16(v - __bfloat162float(hi));
    long base = (long)m * K3;
    g_A3[base + k] = hi;
    g_A3[base + 1024 + k] = hi;
    g_A3[base + 2048 + k] = lo;
}

template<int WHICH>
__global__ void conv_B3(const float* __restrict__ W)
{
    const int N = WHICH ? 1024 : 3072;
    __nv_bfloat16* dst = WHICH ? g_B3p : g_B3;
    int i = blockIdx.x * blockDim.x + threadIdx.x;
    if (i >= CQ * N) return;
    int k = i / N, n = i - k * N;
    float v = W[i];
    __nv_bfloat16 hi = __float2bfloat16(v);
    __nv_bfloat16 lo = __float2bfloat16(v - __bfloat162float(hi));
    dst[(long)k * N + n] = hi;
    dst[(long)(1024 + k) * N + n] = lo;
    dst[(long)(2048 + k) * N + n] = hi;
}

// ---------------------------------------------------------------------------
// bf16 tensor-core GEMM, 3-stage cp.async pipeline, dynamic smem.
// Block tile 128x128, BK=32, 256 threads = 8 warps, warp tile 64x32.
// MODE 1: B=g_B3, N=3072, scatter to g_q/g_k/g_v; MODE 2: B=g_B3p, N=1024.
// ---------------------------------------------------------------------------
#define CP_ASYNC16(dst_u32, src_ptr) \
    asm volatile("cp.async.cg.shared.global [%0], [%1], 16;\n" \
                 :: "r"(dst_u32), "l"(src_ptr))
#define CP_COMMIT() asm volatile("cp.async.commit_group;\n")
#define CP_WAIT(n)  asm volatile("cp.async.wait_group %0;\n" :: "n"(n))

template<int MODE>
__global__ __launch_bounds__(256)
void gemm_bf16(const float* __restrict__ bias, float* __restrict__ C)
{
    const int N = (MODE == 1) ? 3072 : 1024;
    const __nv_bfloat16* A = g_A3;
    const __nv_bfloat16* B = (MODE == 1) ? g_B3 : g_B3p;

    extern __shared__ __nv_bfloat16 smem_g[];
    // As[st][128][40], Bs[st][32][136]
    __nv_bfloat16* AsBase = smem_g;                     // 3 * GA_ELE
    __nv_bfloat16* BsBase = smem_g + 3 * GA_ELE;        // 3 * GB_ELE
    #define AS(st, r, c) AsBase[(st) * GA_ELE + (r) * 40 + (c)]
    #define BS(st, r, c) BsBase[(st) * GB_ELE + (r) * 136 + (c)]

    int tid = threadIdx.x;
    int lane = tid & 31;
    int w = tid >> 5;
    int wm = (w & 1) * 64;
    int wn = (w >> 1) * 32;
    int m0 = blockIdx.y * 128;
    int n0 = blockIdx.x * 128;

    int a_r0 = tid >> 2,  a_c = (tid & 3) * 8;
    int b_r0 = tid >> 4,  b_c = (tid & 15) * 8;

    float acc[4][4][4];
    #pragma unroll
    for (int i = 0; i < 4; i++)
        #pragma unroll
        for (int j = 0; j < 4; j++)
            #pragma unroll
            for (int f = 0; f < 4; f++) acc[i][j][f] = 0.f;

    const int NIT = K3 / 32;

    // prefetch stages 0, 1
    #pragma unroll
    for (int st = 0; st < 2; st++) {
        int k0 = st * 32;
        #pragma unroll
        for (int p = 0; p < 2; p++) {
            int ar = a_r0 + p * 64;
            uint32_t d = (uint32_t)__cvta_generic_to_shared(&AS(st, ar, a_c));
            CP_ASYNC16(d, &A[(long)(m0 + ar) * K3 + k0 + a_c]);
            int br = b_r0 + p * 16;
            uint32_t d2 = (uint32_t)__cvta_generic_to_shared(&BS(st, br, b_c));
            CP_ASYNC16(d2, &B[(long)(k0 + br) * N + n0 + b_c]);
        }
        CP_COMMIT();
    }

    for (int it = 0; it < NIT; it++) {
        int s = it % 3;
        if (it + 1 < NIT) { CP_WAIT(1); } else { CP_WAIT(0); }
        __syncthreads();

        // prefetch stage it+2 (slot (it-1)%3, retired by the sync above)
        if (it + 2 < NIT) {
            int k0 = (it + 2) * 32;
            int sn = (it + 2) % 3;
            #pragma unroll
            for (int p = 0; p < 2; p++) {
                int ar = a_r0 + p * 64;
                uint32_t d = (uint32_t)__cvta_generic_to_shared(&AS(sn, ar, a_c));
                CP_ASYNC16(d, &A[(long)(m0 + ar) * K3 + k0 + a_c]);
                int br = b_r0 + p * 16;
                uint32_t d2 = (uint32_t)__cvta_generic_to_shared(&BS(sn, br, b_c));
                CP_ASYNC16(d2, &B[(long)(k0 + br) * N + n0 + b_c]);
            }
            CP_COMMIT();
        }

        #pragma unroll
        for (int kk = 0; kk < 2; kk++) {
            int kb = kk * 16;
            uint32_t a[4][4], b[2][4];
            #pragma unroll
            for (int mi = 0; mi < 4; mi++) {
                uint32_t addr = (uint32_t)__cvta_generic_to_shared(
                    &AS(s, wm + mi * 16 + (lane & 15), kb + (lane >> 4) * 8));
                asm volatile("ldmatrix.sync.aligned.m8n8.x4.shared.b16 {%0,%1,%2,%3},[%4];"
                             : "=r"(a[mi][0]), "=r"(a[mi][1]), "=r"(a[mi][2]), "=r"(a[mi][3])
                             : "r"(addr));
            }
            #pragma unroll
            for (int nj = 0; nj < 2; nj++) {
                uint32_t addr = (uint32_t)__cvta_generic_to_shared(
                    &BS(s, kb + (lane & 15), wn + nj * 16 + (lane >> 4) * 8));
                asm volatile("ldmatrix.sync.aligned.m8n8.x4.trans.shared.b16 {%0,%1,%2,%3},[%4];"
                             : "=r"(b[nj][0]), "=r"(b[nj][1]), "=r"(b[nj][2]), "=r"(b[nj][3])
                             : "r"(addr));
            }
            #pragma unroll
            for (int mi = 0; mi < 4; mi++)
                #pragma unroll
                for (int ni = 0; ni < 4; ni++) {
                    uint32_t b0 = b[ni >> 1][(ni & 1) * 2 + 0];
                    uint32_t b1 = b[ni >> 1][(ni & 1) * 2 + 1];
                    float* d = acc[mi][ni];
                    asm volatile(
                        "mma.sync.aligned.m16n8k16.row.col.f32.bf16.bf16.f32 "
                        "{%0,%1,%2,%3},{%4,%5,%6,%7},{%8,%9},{%0,%1,%2,%3};"
                        : "+f"(d[0]), "+f"(d[1]), "+f"(d[2]), "+f"(d[3])
                        : "r"(a[mi][0]), "r"(a[mi][1]), "r"(a[mi][2]), "r"(a[mi][3]),
                          "r"(b0), "r"(b1));
                }
        }
    }

    #pragma unroll
    for (int mi = 0; mi < 4; mi++)
        #pragma unroll
        for (int ni = 0; ni < 4; ni++)
            #pragma unroll
            for (int f = 0; f < 4; f++) {
                int m = m0 + wm + mi * 16 + (lane >> 2) + (f >> 1) * 8;
                int n = n0 + wn + ni * 8 + (lane & 3) * 2 + (f & 1);
                float v = acc[mi][ni][f] + bias[n];
                if (MODE == 1) {
                    int which = n >> 10;
                    int cc = n & 1023;
                    int h = cc >> 6;
                    int d = cc & 63;
                    int bb = m >> 11;
                    int t = m & 2047;
                    float* dst = (which == 0) ? g_q : ((which == 1) ? g_k : g_v);
                    dst[(((bb << 4) + h) * (long)TQ + t) * DQ + d] = v;
                } else {
                    C[(long)m * N + n] = v;
                }
            }
    #undef AS
    #undef BS
}

// ---------------------------------------------------------------------------
// RoPE: fp32 q/k -> fp16 q (pre-scaled 1/8), fp16 k, fp16 v (coalesced).
// ---------------------------------------------------------------------------
__global__ void rope_kernel()
{
    int idx = blockIdx.x * blockDim.x + threadIdx.x;
    int lane = idx & 31;
    int row = idx >> 5;
    if (row >= BH * TQ) return;
    int t = row & (TQ - 1);

    float inv_freq = 1.0f / powf(10000.0f, (float)(2 * lane) / 64.0f);
    float ang = (float)t * inv_freq;
    float c = cosf(ang);
    float s = sinf(ang);

    const float* qp = g_q + (long)row * DQ;
    float q0 = qp[lane], q1 = qp[lane + 32];
    g_qh[(long)row * DQ + lane]      = __float2half((q0 * c - q1 * s) * 0.125f);
    g_qh[(long)row * DQ + lane + 32] = __float2half((q1 * c + q0 * s) * 0.125f);

    const float* kp = g_k + (long)row * DQ;
    float k0 = kp[lane], k1 = kp[lane + 32];
    g_kh[(long)row * DQ + lane]      = __float2half(k0 * c - k1 * s);
    g_kh[(long)row * DQ + lane + 32] = __float2half(k1 * c + k0 * s);

    const float* vp = g_v + (long)row * DQ;
    g_vh[(long)row * DQ + lane]      = __float2half(vp[lane]);
    g_vh[(long)row * DQ + lane + 32] = __float2half(vp[lane + 32]);
}

// ---------------------------------------------------------------------------
// fp16 tensor-core flash attention; epilogue writes hi/lo bf16 split
// directly into g_A3 (fused conv; g_y eliminated).
// ---------------------------------------------------------------------------
__global__ __launch_bounds__(128)
void flash_attn_h()
{
    __shared__ __half Qs[64][72];
    __shared__ __half Ks[64][72];
    __shared__ __half Vs[64][72];

    int bh = blockIdx.x;
    int y  = gridDim.y - 1 - blockIdx.y;   // heavy tiles first
    int tid = threadIdx.x;
    int w = tid >> 5;
    int lane = tid & 31;

    const __half* qb = g_qh + (long)bh * TQ * DQ;
    const __half* kb = g_kh + (long)bh * TQ * DQ;
    const __half* vb = g_vh + (long)bh * TQ * DQ;

    #pragma unroll
    for (int p = 0; p < 4; p++) {
        int idx = tid + p * 128;
        int r = idx >> 3, c = (idx & 7) * 8;
        *(float4*)&Qs[r][c] = *(const float4*)&qb[(long)(y * 64 + r) * DQ + c];
    }
    __syncthreads();

    uint32_t qf[4][4];
    #pragma unroll
    for (int t = 0; t < 4; t++) {
        uint32_t addr = (uint32_t)__cvta_generic_to_shared(
            &Qs[w * 16 + (lane & 15)][t * 16 + (lane >> 4) * 8]);
        asm volatile("ldmatrix.sync.aligned.m8n8.x4.shared.b16 {%0,%1,%2,%3},[%4];"
                     : "=r"(qf[t][0]), "=r"(qf[t][1]), "=r"(qf[t][2]), "=r"(qf[t][3])
                     : "r"(addr));
    }

    float o[8][4];
    #pragma unroll
    for (int i = 0; i < 8; i++)
        #pragma unroll
        for (int f = 0; f < 4; f++) o[i][f] = 0.f;
    float m0 = -1e30f, m1 = -1e30f, l0 = 0.f, l1 = 0.f;

    for (int kc = 0; kc <= y; kc++) {
        __syncthreads();
        #pragma unroll
        for (int p = 0; p < 4; p++) {
            int idx = tid + p * 128;
            int r = idx >> 3, c = (idx & 7) * 8;
            *(float4*)&Ks[r][c] = *(const float4*)&kb[(long)(kc * 64 + r) * DQ + c];
            *(float4*)&Vs[r][c] = *(const float4*)&vb[(long)(kc * 64 + r) * DQ + c];
        }
        __syncthreads();

        float s[8][4];
        #pragma unroll
        for (int i = 0; i < 8; i++)
            #pragma unroll
            for (int f = 0; f < 4; f++) s[i][f] = 0.f;

        #pragma unroll
        for (int t = 0; t < 4; t++) {
            #pragma unroll
            for (int kj = 0; kj < 4; kj++) {
                uint32_t r[4];
                uint32_t addr = (uint32_t)__cvta_generic_to_shared(
                    &Ks[kj * 16 + (lane & 15)][t * 16 + (lane >> 4) * 8]);
                asm volatile("ldmatrix.sync.aligned.m8n8.x4.shared.b16 {%0,%1,%2,%3},[%4];"
                             : "=r"(r[0]), "=r"(r[1]), "=r"(r[2]), "=r"(r[3])
                             : "r"(addr));
                asm volatile(
                    "mma.sync.aligned.m16n8k16.row.col.f32.f16.f16.f32 "
                    "{%0,%1,%2,%3},{%4,%5,%6,%7},{%8,%9},{%0,%1,%2,%3};"
                    : "+f"(s[2*kj][0]), "+f"(s[2*kj][1]), "+f"(s[2*kj][2]), "+f"(s[2*kj][3])
                    : "r"(qf[t][0]), "r"(qf[t][1]), "r"(qf[t][2]), "r"(qf[t][3]),
                      "r"(r[0]), "r"(r[2]));
                asm volatile(
                    "mma.sync.aligned.m16n8k16.row.col.f32.f16.f16.f32 "
                    "{%0,%1,%2,%3},{%4,%5,%6,%7},{%8,%9},{%0,%1,%2,%3};"
                    : "+f"(s[2*kj+1][0]), "+f"(s[2*kj+1][1]), "+f"(s[2*kj+1][2]), "+f"(s[2*kj+1][3])
                    : "r"(qf[t][0]), "r"(qf[t][1]), "r"(qf[t][2]), "r"(qf[t][3]),
                      "r"(r[1]), "r"(r[3]));
            }
        }

        if (kc == y) {
            int qr0 = y * 64 + w * 16 + (lane >> 2);
            int qr1 = qr0 + 8;
            #pragma unroll
            for (int ni = 0; ni < 8; ni++) {
                int kcol = kc * 64 + ni * 8 + ((lane & 3) << 1);
                if (kcol     > qr0) s[ni][0] = -1e30f;
                if (kcol + 1 > qr0) s[ni][1] = -1e30f;
                if (kcol     > qr1) s[ni][2] = -1e30f;
                if (kcol + 1 > qr1) s[ni][3] = -1e30f;
            }
        }

        float mx0 = -1e30f, mx1 = -1e30f;
        #pragma unroll
        for (int ni = 0; ni < 8; ni++) {
            mx0 = fmaxf(mx0, fmaxf(s[ni][0], s[ni][1]));
            mx1 = fmaxf(mx1, fmaxf(s[ni][2], s[ni][3]));
        }
        mx0 = fmaxf(mx0, __shfl_xor_sync(0xffffffffu, mx0, 1));
        mx0 = fmaxf(mx0, __shfl_xor_sync(0xffffffffu, mx0, 2));
        mx1 = fmaxf(mx1, __shfl_xor_sync(0xffffffffu, mx1, 1));
        mx1 = fmaxf(mx1, __shfl_xor_sync(0xffffffffu, mx1, 2));
        float mn0 = fmaxf(m0, mx0), mn1 = fmaxf(m1, mx1);
        float a0 = __expf(m0 - mn0), a1 = __expf(m1 - mn1);
        m0 = mn0; m1 = mn1;

        float ls0 = 0.f, ls1 = 0.f;
        uint32_t pf01[8], pf23[8];
        #pragma unroll
        for (int ni = 0; ni < 8; ni++) {
            float p0 = __expf(s[ni][0] - mn0);
            float p1 = __expf(s[ni][1] - mn0);
            float p2 = __expf(s[ni][2] - mn1);
            float p3 = __expf(s[ni][3] - mn1);
            ls0 += p0 + p1;
            ls1 += p2 + p3;
            __half2 h01 = __floats2half2_rn(p0, p1);
            __half2 h23 = __floats2half2_rn(p2, p3);
            pf01[ni] = *(uint32_t*)&h01;
            pf23[ni] = *(uint32_t*)&h23;
        }
        l0 = l0 * a0 + ls0;
        l1 = l1 * a1 + ls1;
        #pragma unroll
        for (int ni = 0; ni < 8; ni++) {
            o[ni][0] *= a0; o[ni][1] *= a0;
            o[ni][2] *= a1; o[ni][3] *= a1;
        }

        #pragma unroll
        for (int t = 0; t < 4; t++) {
            uint32_t vf[4][4];
            #pragma unroll
            for (int dj = 0; dj < 4; dj++) {
                uint32_t addr = (uint32_t)__cvta_generic_to_shared(
                    &Vs[t * 16 + (lane & 15)][dj * 16 + (lane >> 4) * 8]);
                asm volatile("ldmatrix.sync.aligned.m8n8.x4.trans.shared.b16 {%0,%1,%2,%3},[%4];"
                             : "=r"(vf[dj][0]), "=r"(vf[dj][1]), "=r"(vf[dj][2]), "=r"(vf[dj][3])
                             : "r"(addr));
            }
            uint32_t pa0 = pf01[2 * t], pa1 = pf23[2 * t];
            uint32_t pa2 = pf01[2 * t + 1], pa3 = pf23[2 * t + 1];
            #pragma unroll
            for (int ni = 0; ni < 8; ni++) {
                uint32_t b0 = vf[ni >> 1][(ni & 1) * 2 + 0];
                uint32_t b1 = vf[ni >> 1][(ni & 1) * 2 + 1];
                asm volatile(
                    "mma.sync.aligned.m16n8k16.row.col.f32.f16.f16.f32 "
                    "{%0,%1,%2,%3},{%4,%5,%6,%7},{%8,%9},{%0,%1,%2,%3};"
                    : "+f"(o[ni][0]), "+f"(o[ni][1]), "+f"(o[ni][2]), "+f"(o[ni][3])
                    : "r"(pa0), "r"(pa1), "r"(pa2), "r"(pa3),
                      "r"(b0), "r"(b1));
            }
        }
    }

    l0 += __shfl_xor_sync(0xffffffffu, l0, 1);
    l0 += __shfl_xor_sync(0xffffffffu, l0, 2);
    l1 += __shfl_xor_sync(0xffffffffu, l1, 1);
    l1 += __shfl_xor_sync(0xffffffffu, l1, 2);
    float inv0 = 1.0f / l0, inv1 = 1.0f / l1;

    // fused epilogue: hi/lo split straight into g_A3
    int b = bh >> 4, h = bh & 15;
    int r0 = y * 64 + w * 16 + (lane >> 2);
    long mrow0 = (long)(b * TQ + r0) * K3;
    long mrow1 = (long)(b * TQ + r0 + 8) * K3;
    #pragma unroll
    for (int ni = 0; ni < 8; ni++) {
        int cc = h * 64 + ni * 8 + ((lane & 3) << 1);
        float v0x = o[ni][0] * inv0, v0y = o[ni][1] * inv0;
        float v1x = o[ni][2] * inv1, v1y = o[ni][3] * inv1;

        __nv_bfloat16 h0x = __float2bfloat16(v0x);
        __nv_bfloat16 h0y = __float2bfloat16(v0y);
        __nv_bfloat162 hi0; hi0.x = h0x; hi0.y = h0y;
        __nv_bfloat162 lo0;
        lo0.x = __float2bfloat16(v0x - __bfloat162float(h0x));
        lo0.y = __float2bfloat16(v0y - __bfloat162float(h0y));
        *(__nv_bfloat162*)&g_A3[mrow0 + cc]        = hi0;
        *(__nv_bfloat162*)&g_A3[mrow0 + 1024 + cc] = hi0;
        *(__nv_bfloat162*)&g_A3[mrow0 + 2048 + cc] = lo0;

        __nv_bfloat16 h1x = __float2bfloat16(v1x);
        __nv_bfloat16 h1y = __float2bfloat16(v1y);
        __nv_bfloat162 hi1; hi1.x = h1x; hi1.y = h1y;
        __nv_bfloat162 lo1;
        lo1.x = __float2bfloat16(v1x - __bfloat162float(h1x));
        lo1.y = __float2bfloat16(v1y - __bfloat162float(h1y));
        *(__nv_bfloat162*)&g_A3[mrow1 + cc]        = hi1;
        *(__nv_bfloat162*)&g_A3[mrow1 + 1024 + cc] = hi1;
        *(__nv_bfloat162*)&g_A3[mrow1 + 2048 + cc] = lo1;
    }
}

// ---------------------------------------------------------------------------
extern "C" void kernel_launch(void* const* d_in, const int* in_sizes, int n_in,
                              void* d_out, int out_size)
{
    const float* x     = (const float*)d_in[0];
    const float* Wqkv  = (const float*)d_in[1];
    const float* bqkv  = (const float*)d_in[2];
    const float* Wproj = (const float*)d_in[3];
    const float* bproj = (const float*)d_in[4];
    float* out = (float*)d_out;

    // raise dynamic smem cap for the GEMM (idempotent host call, capture-safe)
    cudaFuncSetAttribute(gemm_bf16<1>, cudaFuncAttributeMaxDynamicSharedMemorySize,
                         GEMM_SMEM_BYTES);
    cudaFuncSetAttribute(gemm_bf16<2>, cudaFuncAttributeMaxDynamicSharedMemorySize,
                         GEMM_SMEM_BYTES);

    conv_A3<<<(M_ROWS * CQ) / 256, 256>>>(x);
    conv_B3<0><<<(CQ * 3072) / 256, 256>>>(Wqkv);
    conv_B3<1><<<(CQ * 1024) / 256, 256>>>(Wproj);
    gemm_bf16<1><<<dim3(3072 / 128, M_ROWS / 128), 256, GEMM_SMEM_BYTES>>>(bqkv, nullptr);

    rope_kernel<<<(BH * TQ * 32) / 256, 256>>>();
    flash_attn_h<<<dim3(BH, TQ / 64), 128>>>();   // writes g_A3 directly

    gemm_bf16<2><<<dim3(1024 / 128, M_ROWS / 128), 256, GEMM_SMEM_BYTES>>>(bproj, out);
}

// round 12
// speedup vs baseline: 1.1067x; 1.1067x over previous
#include <cuda_runtime.h>
#include <cuda_bf16.h>
#include <cuda_fp16.h>
#include <stdint.h>
#include <math.h>

#define BQ 2
#define TQ 2048
#define CQ 1024
#define HQ 16
#define DQ 64
#define BH (BQ*HQ)
#define M_ROWS 4096
#define K3 3072

// GEMM dynamic smem: 2 stages x (A 128x72 + B 64x136) bf16 = 71680 B
#define GA_ELE (128*72)
#define GB_ELE (64*136)
#define GEMM_SMEM_BYTES (2 * (GA_ELE + GB_ELE) * 2)

// Scratch (allocation-free rule: static device globals)
__device__ float g_q[BQ*HQ*TQ*DQ];
__device__ float g_k[BQ*HQ*TQ*DQ];
__device__ float g_v[BQ*HQ*TQ*DQ];
__device__ __half g_qh[BQ*HQ*TQ*DQ];
__device__ __half g_kh[BQ*HQ*TQ*DQ];
__device__ __half g_vh[BQ*HQ*TQ*DQ];
__device__ __nv_bfloat16 g_A3[(long)M_ROWS * K3];     // [M][K3]
__device__ __nv_bfloat16 g_B3[(long)K3 * 3072];       // qkv W split [K3][3072]
__device__ __nv_bfloat16 g_B3p[(long)K3 * 1024];      // proj W split [K3][1024]

#define CP_ASYNC16(dst_u32, src_ptr) \
    asm volatile("cp.async.cg.shared.global [%0], [%1], 16;\n" \
                 :: "r"(dst_u32), "l"(src_ptr))
#define CP_COMMIT() asm volatile("cp.async.commit_group;\n")
#define CP_WAIT(n)  asm volatile("cp.async.wait_group %0;\n" :: "n"(n))

// ---------------------------------------------------------------------------
// fp32 -> (hi, lo) bf16 split conversions.
// ---------------------------------------------------------------------------
__global__ void conv_A3(const float* __restrict__ src)
{
    int i = blockIdx.x * blockDim.x + threadIdx.x;
    if (i >= M_ROWS * CQ) return;
    int m = i >> 10, k = i & 1023;
    float v = src[i];
    __nv_bfloat16 hi = __float2bfloat16(v);
    __nv_bfloat16 lo = __float2bfloat16(v - __bfloat162float(hi));
    long base = (long)m * K3;
    g_A3[base + k] = hi;
    g_A3[base + 1024 + k] = hi;
    g_A3[base + 2048 + k] = lo;
}

template<int WHICH>
__global__ void conv_B3(const float* __restrict__ W)
{
    const int N = WHICH ? 1024 : 3072;
    __nv_bfloat16* dst = WHICH ? g_B3p : g_B3;
    int i = blockIdx.x * blockDim.x + threadIdx.x;
    if (i >= CQ * N) return;
    int k = i / N, n = i - k * N;
    float v = W[i];
    __nv_bfloat16 hi = __float2bfloat16(v);
    __nv_bfloat16 lo = __float2bfloat16(v - __bfloat162float(hi));
    dst[(long)k * N + n] = hi;
    dst[(long)(1024 + k) * N + n] = lo;
    dst[(long)(2048 + k) * N + n] = hi;
}

// ---------------------------------------------------------------------------
// bf16 mma.sync GEMM, 2-stage cp.async, BK=64.
// Block tile 128x128, 256 threads = 8 warps (2m x 4n), warp tile 64x32.
// MODE 1: B=g_B3, N=3072, scatter q/k/v; MODE 2: B=g_B3p, N=1024, write C.
// ---------------------------------------------------------------------------
template<int MODE>
__global__ __launch_bounds__(256)
void gemm_bf16(const float* __restrict__ bias, float* __restrict__ C)
{
    const int N = (MODE == 1) ? 3072 : 1024;
    const __nv_bfloat16* A = g_A3;
    const __nv_bfloat16* B = (MODE == 1) ? g_B3 : g_B3p;

    extern __shared__ __nv_bfloat16 smem_g[];
    __nv_bfloat16* AsBase = smem_g;                 // 2 * GA_ELE
    __nv_bfloat16* BsBase = smem_g + 2 * GA_ELE;    // 2 * GB_ELE
    #define AS(st, r, c) AsBase[(st) * GA_ELE + (r) * 72 + (c)]
    #define BS(st, r, c) BsBase[(st) * GB_ELE + (r) * 136 + (c)]

    int tid = threadIdx.x;
    int lane = tid & 31;
    int w = tid >> 5;
    int wm = (w & 1) * 64;
    int wn = (w >> 1) * 32;
    int m0 = blockIdx.y * 128;
    int n0 = blockIdx.x * 128;

    int a_r0 = tid >> 3,  a_c = (tid & 7) * 8;     // A: 128r x 64c, 4 passes (+32 rows)
    int b_r0 = tid >> 4,  b_c = (tid & 15) * 8;    // B: 64r x 128c, 4 passes (+16 rows)

    float acc[4][4][4];
    #pragma unroll
    for (int i = 0; i < 4; i++)
        #pragma unroll
        for (int j = 0; j < 4; j++)
            #pragma unroll
            for (int f = 0; f < 4; f++) acc[i][j][f] = 0.f;

    const int NIT = K3 / 64;   // 48

    // prefetch stage 0
    {
        #pragma unroll
        for (int p = 0; p < 4; p++) {
            int ar = a_r0 + p * 32;
            uint32_t d = (uint32_t)__cvta_generic_to_shared(&AS(0, ar, a_c));
            CP_ASYNC16(d, &A[(long)(m0 + ar) * K3 + a_c]);
            int br = b_r0 + p * 16;
            uint32_t d2 = (uint32_t)__cvta_generic_to_shared(&BS(0, br, b_c));
            CP_ASYNC16(d2, &B[(long)br * N + n0 + b_c]);
        }
        CP_COMMIT();
    }

    for (int it = 0; it < NIT; it++) {
        int s = it & 1;
        // prefetch next stage (other buffer; all warps passed the barrier that
        // retired its previous contents)
        if (it + 1 < NIT) {
            int k0 = (it + 1) * 64;
            int sn = s ^ 1;
            #pragma unroll
            for (int p = 0; p < 4; p++) {
                int ar = a_r0 + p * 32;
                uint32_t d = (uint32_t)__cvta_generic_to_shared(&AS(sn, ar, a_c));
                CP_ASYNC16(d, &A[(long)(m0 + ar) * K3 + k0 + a_c]);
                int br = b_r0 + p * 16;
                uint32_t d2 = (uint32_t)__cvta_generic_to_shared(&BS(sn, br, b_c));
                CP_ASYNC16(d2, &B[(long)(k0 + br) * N + n0 + b_c]);
            }
            CP_COMMIT();
            CP_WAIT(1);
        } else {
            CP_WAIT(0);
        }
        __syncthreads();

        #pragma unroll
        for (int kk = 0; kk < 4; kk++) {
            int kb = kk * 16;
            uint32_t a[4][4], b[2][4];
            #pragma unroll
            for (int mi = 0; mi < 4; mi++) {
                uint32_t addr = (uint32_t)__cvta_generic_to_shared(
                    &AS(s, wm + mi * 16 + (lane & 15), kb + (lane >> 4) * 8));
                asm volatile("ldmatrix.sync.aligned.m8n8.x4.shared.b16 {%0,%1,%2,%3},[%4];"
                             : "=r"(a[mi][0]), "=r"(a[mi][1]), "=r"(a[mi][2]), "=r"(a[mi][3])
                             : "r"(addr));
            }
            #pragma unroll
            for (int nj = 0; nj < 2; nj++) {
                uint32_t addr = (uint32_t)__cvta_generic_to_shared(
                    &BS(s, kb + (lane & 15), wn + nj * 16 + (lane >> 4) * 8));
                asm volatile("ldmatrix.sync.aligned.m8n8.x4.trans.shared.b16 {%0,%1,%2,%3},[%4];"
                             : "=r"(b[nj][0]), "=r"(b[nj][1]), "=r"(b[nj][2]), "=r"(b[nj][3])
                             : "r"(addr));
            }
            #pragma unroll
            for (int mi = 0; mi < 4; mi++)
                #pragma unroll
                for (int ni = 0; ni < 4; ni++) {
                    uint32_t b0 = b[ni >> 1][(ni & 1) * 2 + 0];
                    uint32_t b1 = b[ni >> 1][(ni & 1) * 2 + 1];
                    float* d = acc[mi][ni];
                    asm volatile(
                        "mma.sync.aligned.m16n8k16.row.col.f32.bf16.bf16.f32 "
                        "{%0,%1,%2,%3},{%4,%5,%6,%7},{%8,%9},{%0,%1,%2,%3};"
                        : "+f"(d[0]), "+f"(d[1]), "+f"(d[2]), "+f"(d[3])
                        : "r"(a[mi][0]), "r"(a[mi][1]), "r"(a[mi][2]), "r"(a[mi][3]),
                          "r"(b0), "r"(b1));
                }
        }
        __syncthreads();
    }

    #pragma unroll
    for (int mi = 0; mi < 4; mi++)
        #pragma unroll
        for (int ni = 0; ni < 4; ni++)
            #pragma unroll
            for (int f = 0; f < 4; f++) {
                int m = m0 + wm + mi * 16 + (lane >> 2) + (f >> 1) * 8;
                int n = n0 + wn + ni * 8 + (lane & 3) * 2 + (f & 1);
                float v = acc[mi][ni][f] + bias[n];
                if (MODE == 1) {
                    int which = n >> 10;
                    int cc = n & 1023;
                    int h = cc >> 6;
                    int d = cc & 63;
                    int bb = m >> 11;
                    int t = m & 2047;
                    float* dst = (which == 0) ? g_q : ((which == 1) ? g_k : g_v);
                    dst[(((bb << 4) + h) * (long)TQ + t) * DQ + d] = v;
                } else {
                    C[(long)m * N + n] = v;
                }
            }
    #undef AS
    #undef BS
}

// ---------------------------------------------------------------------------
// RoPE: fp32 q/k -> fp16 q (pre-scaled 1/8), fp16 k, fp16 v (coalesced).
// ---------------------------------------------------------------------------
__global__ void rope_kernel()
{
    int idx = blockIdx.x * blockDim.x + threadIdx.x;
    int lane = idx & 31;
    int row = idx >> 5;
    if (row >= BH * TQ) return;
    int t = row & (TQ - 1);

    float inv_freq = 1.0f / powf(10000.0f, (float)(2 * lane) / 64.0f);
    float ang = (float)t * inv_freq;
    float c = cosf(ang);
    float s = sinf(ang);

    const float* qp = g_q + (long)row * DQ;
    float q0 = qp[lane], q1 = qp[lane + 32];
    g_qh[(long)row * DQ + lane]      = __float2half((q0 * c - q1 * s) * 0.125f);
    g_qh[(long)row * DQ + lane + 32] = __float2half((q1 * c + q0 * s) * 0.125f);

    const float* kp = g_k + (long)row * DQ;
    float k0 = kp[lane], k1 = kp[lane + 32];
    g_kh[(long)row * DQ + lane]      = __float2half(k0 * c - k1 * s);
    g_kh[(long)row * DQ + lane + 32] = __float2half(k1 * c + k0 * s);

    const float* vp = g_v + (long)row * DQ;
    g_vh[(long)row * DQ + lane]      = __float2half(vp[lane]);
    g_vh[(long)row * DQ + lane + 32] = __float2half(vp[lane + 32]);
}

// ---------------------------------------------------------------------------
// fp16 tensor-core flash attention; epilogue writes hi/lo bf16 split
// directly into g_A3 rows for the proj GEMM.
// ---------------------------------------------------------------------------
__global__ __launch_bounds__(128)
void flash_attn_h()
{
    __shared__ __half Qs[64][72];
    __shared__ __half Ks[64][72];
    __shared__ __half Vs[64][72];

    int bh = blockIdx.x;
    int y  = gridDim.y - 1 - blockIdx.y;
    int tid = threadIdx.x;
    int w = tid >> 5;
    int lane = tid & 31;

    const __half* qb = g_qh + (long)bh * TQ * DQ;
    const __half* kb = g_kh + (long)bh * TQ * DQ;
    const __half* vb = g_vh + (long)bh * TQ * DQ;

    #pragma unroll
    for (int p = 0; p < 4; p++) {
        int idx = tid + p * 128;
        int r = idx >> 3, c = (idx & 7) * 8;
        *(float4*)&Qs[r][c] = *(const float4*)&qb[(long)(y * 64 + r) * DQ + c];
    }
    __syncthreads();

    uint32_t qf[4][4];
    #pragma unroll
    for (int t = 0; t < 4; t++) {
        uint32_t addr = (uint32_t)__cvta_generic_to_shared(
            &Qs[w * 16 + (lane & 15)][t * 16 + (lane >> 4) * 8]);
        asm volatile("ldmatrix.sync.aligned.m8n8.x4.shared.b16 {%0,%1,%2,%3},[%4];"
                     : "=r"(qf[t][0]), "=r"(qf[t][1]), "=r"(qf[t][2]), "=r"(qf[t][3])
                     : "r"(addr));
    }

    float o[8][4];
    #pragma unroll
    for (int i = 0; i < 8; i++)
        #pragma unroll
        for (int f = 0; f < 4; f++) o[i][f] = 0.f;
    float m0 = -1e30f, m1 = -1e30f, l0 = 0.f, l1 = 0.f;

    for (int kc = 0; kc <= y; kc++) {
        __syncthreads();
        #pragma unroll
        for (int p = 0; p < 4; p++) {
            int idx = tid + p * 128;
            int r = idx >> 3, c = (idx & 7) * 8;
            *(float4*)&Ks[r][c] = *(const float4*)&kb[(long)(kc * 64 + r) * DQ + c];
            *(float4*)&Vs[r][c] = *(const float4*)&vb[(long)(kc * 64 + r) * DQ + c];
        }
        __syncthreads();

        float s[8][4];
        #pragma unroll
        for (int i = 0; i < 8; i++)
            #pragma unroll
            for (int f = 0; f < 4; f++) s[i][f] = 0.f;

        #pragma unroll
        for (int t = 0; t < 4; t++) {
            #pragma unroll
            for (int kj = 0; kj < 4; kj++) {
                uint32_t r[4];
                uint32_t addr = (uint32_t)__cvta_generic_to_shared(
                    &Ks[kj * 16 + (lane & 15)][t * 16 + (lane >> 4) * 8]);
                asm volatile("ldmatrix.sync.aligned.m8n8.x4.shared.b16 {%0,%1,%2,%3},[%4];"
                             : "=r"(r[0]), "=r"(r[1]), "=r"(r[2]), "=r"(r[3])
                             : "r"(addr));
                asm volatile(
                    "mma.sync.aligned.m16n8k16.row.col.f32.f16.f16.f32 "
                    "{%0,%1,%2,%3},{%4,%5,%6,%7},{%8,%9},{%0,%1,%2,%3};"
                    : "+f"(s[2*kj][0]), "+f"(s[2*kj][1]), "+f"(s[2*kj][2]), "+f"(s[2*kj][3])
                    : "r"(qf[t][0]), "r"(qf[t][1]), "r"(qf[t][2]), "r"(qf[t][3]),
                      "r"(r[0]), "r"(r[2]));
                asm volatile(
                    "mma.sync.aligned.m16n8k16.row.col.f32.f16.f16.f32 "
                    "{%0,%1,%2,%3},{%4,%5,%6,%7},{%8,%9},{%0,%1,%2,%3};"
                    : "+f"(s[2*kj+1][0]), "+f"(s[2*kj+1][1]), "+f"(s[2*kj+1][2]), "+f"(s[2*kj+1][3])
                    : "r"(qf[t][0]), "r"(qf[t][1]), "r"(qf[t][2]), "r"(qf[t][3]),
                      "r"(r[1]), "r"(r[3]));
            }
        }

        if (kc == y) {
            int qr0 = y * 64 + w * 16 + (lane >> 2);
            int qr1 = qr0 + 8;
            #pragma unroll
            for (int ni = 0; ni < 8; ni++) {
                int kcol = kc * 64 + ni * 8 + ((lane & 3) << 1);
                if (kcol     > qr0) s[ni][0] = -1e30f;
                if (kcol + 1 > qr0) s[ni][1] = -1e30f;
                if (kcol     > qr1) s[ni][2] = -1e30f;
                if (kcol + 1 > qr1) s[ni][3] = -1e30f;
            }
        }

        float mx0 = -1e30f, mx1 = -1e30f;
        #pragma unroll
        for (int ni = 0; ni < 8; ni++) {
            mx0 = fmaxf(mx0, fmaxf(s[ni][0], s[ni][1]));
            mx1 = fmaxf(mx1, fmaxf(s[ni][2], s[ni][3]));
        }
        mx0 = fmaxf(mx0, __shfl_xor_sync(0xffffffffu, mx0, 1));
        mx0 = fmaxf(mx0, __shfl_xor_sync(0xffffffffu, mx0, 2));
        mx1 = fmaxf(mx1, __shfl_xor_sync(0xffffffffu, mx1, 1));
        mx1 = fmaxf(mx1, __shfl_xor_sync(0xffffffffu, mx1, 2));
        float mn0 = fmaxf(m0, mx0), mn1 = fmaxf(m1, mx1);
        float a0 = __expf(m0 - mn0), a1 = __expf(m1 - mn1);
        m0 = mn0; m1 = mn1;

        float ls0 = 0.f, ls1 = 0.f;
        uint32_t pf01[8], pf23[8];
        #pragma unroll
        for (int ni = 0; ni < 8; ni++) {
            float p0 = __expf(s[ni][0] - mn0);
            float p1 = __expf(s[ni][1] - mn0);
            float p2 = __expf(s[ni][2] - mn1);
            float p3 = __expf(s[ni][3] - mn1);
            ls0 += p0 + p1;
            ls1 += p2 + p3;
            __half2 h01 = __floats2half2_rn(p0, p1);
            __half2 h23 = __floats2half2_rn(p2, p3);
            pf01[ni] = *(uint32_t*)&h01;
            pf23[ni] = *(uint32_t*)&h23;
        }
        l0 = l0 * a0 + ls0;
        l1 = l1 * a1 + ls1;
        #pragma unroll
        for (int ni = 0; ni < 8; ni++) {
            o[ni][0] *= a0; o[ni][1] *= a0;
            o[ni][2] *= a1; o[ni][3] *= a1;
        }

        #pragma unroll
        for (int t = 0; t < 4; t++) {
            uint32_t vf[4][4];
            #pragma unroll
            for (int dj = 0; dj < 4; dj++) {
                uint32_t addr = (uint32_t)__cvta_generic_to_shared(
                    &Vs[t * 16 + (lane & 15)][dj * 16 + (lane >> 4) * 8]);
                asm volatile("ldmatrix.sync.aligned.m8n8.x4.trans.shared.b16 {%0,%1,%2,%3},[%4];"
                             : "=r"(vf[dj][0]), "=r"(vf[dj][1]), "=r"(vf[dj][2]), "=r"(vf[dj][3])
                             : "r"(addr));
            }
            uint32_t pa0 = pf01[2 * t], pa1 = pf23[2 * t];
            uint32_t pa2 = pf01[2 * t + 1], pa3 = pf23[2 * t + 1];
            #pragma unroll
            for (int ni = 0; ni < 8; ni++) {
                uint32_t b0 = vf[ni >> 1][(ni & 1) * 2 + 0];
                uint32_t b1 = vf[ni >> 1][(ni & 1) * 2 + 1];
                asm volatile(
                    "mma.sync.aligned.m16n8k16.row.col.f32.f16.f16.f32 "
                    "{%0,%1,%2,%3},{%4,%5,%6,%7},{%8,%9},{%0,%1,%2,%3};"
                    : "+f"(o[ni][0]), "+f"(o[ni][1]), "+f"(o[ni][2]), "+f"(o[ni][3])
                    : "r"(pa0), "r"(pa1), "r"(pa2), "r"(pa3),
                      "r"(b0), "r"(b1));
            }
        }
    }

    l0 += __shfl_xor_sync(0xffffffffu, l0, 1);
    l0 += __shfl_xor_sync(0xffffffffu, l0, 2);
    l1 += __shfl_xor_sync(0xffffffffu, l1, 1);
    l1 += __shfl_xor_sync(0xffffffffu, l1, 2);
    float inv0 = 1.0f / l0, inv1 = 1.0f / l1;

    int b = bh >> 4, h = bh & 15;
    int r0 = y * 64 + w * 16 + (lane >> 2);
    long mrow0 = (long)(b * TQ + r0) * K3;
    long mrow1 = (long)(b * TQ + r0 + 8) * K3;
    #pragma unroll
    for (int ni = 0; ni < 8; ni++) {
        int cc = h * 64 + ni * 8 + ((lane & 3) << 1);
        float v0x = o[ni][0] * inv0, v0y = o[ni][1] * inv0;
        float v1x = o[ni][2] * inv1, v1y = o[ni][3] * inv1;

        __nv_bfloat16 h0x = __float2bfloat16(v0x);
        __nv_bfloat16 h0y = __float2bfloat16(v0y);
        __nv_bfloat162 hi0; hi0.x = h0x; hi0.y = h0y;
        __nv_bfloat162 lo0;
        lo0.x = __float2bfloat16(v0x - __bfloat162float(h0x));
        lo0.y = __float2bfloat16(v0y - __bfloat162float(h0y));
        *(__nv_bfloat162*)&g_A3[mrow0 + cc]        = hi0;
        *(__nv_bfloat162*)&g_A3[mrow0 + 1024 + cc] = hi0;
        *(__nv_bfloat162*)&g_A3[mrow0 + 2048 + cc] = lo0;

        __nv_bfloat16 h1x = __float2bfloat16(v1x);
        __nv_bfloat16 h1y = __float2bfloat16(v1y);
        __nv_bfloat162 hi1; hi1.x = h1x; hi1.y = h1y;
        __nv_bfloat162 lo1;
        lo1.x = __float2bfloat16(v1x - __bfloat162float(h1x));
        lo1.y = __float2bfloat16(v1y - __bfloat162float(h1y));
        *(__nv_bfloat162*)&g_A3[mrow1 + cc]        = hi1;
        *(__nv_bfloat162*)&g_A3[mrow1 + 1024 + cc] = hi1;
        *(__nv_bfloat162*)&g_A3[mrow1 + 2048 + cc] = lo1;
    }
}

// ---------------------------------------------------------------------------
extern "C" void kernel_launch(void* const* d_in, const int* in_sizes, int n_in,
                              void* d_out, int out_size)
{
    const float* x     = (const float*)d_in[0];
    const float* Wqkv  = (const float*)d_in[1];
    const float* bqkv  = (const float*)d_in[2];
    const float* Wproj = (const float*)d_in[3];
    const float* bproj = (const float*)d_in[4];
    float* out = (float*)d_out;

    cudaFuncSetAttribute(gemm_bf16<1>, cudaFuncAttributeMaxDynamicSharedMemorySize,
                         GEMM_SMEM_BYTES);
    cudaFuncSetAttribute(gemm_bf16<2>, cudaFuncAttributeMaxDynamicSharedMemorySize,
                         GEMM_SMEM_BYTES);

    conv_A3<<<(M_ROWS * CQ) / 256, 256>>>(x);
    conv_B3<0><<<(CQ * 3072) / 256, 256>>>(Wqkv);
    conv_B3<1><<<(CQ * 1024) / 256, 256>>>(Wproj);
    gemm_bf16<1><<<dim3(24, 32), 256, GEMM_SMEM_BYTES>>>(bqkv, nullptr);

    rope_kernel<<<(BH * TQ * 32) / 256, 256>>>();
    flash_attn_h<<<dim3(BH, TQ / 64), 128>>>();   // writes g_A3 directly

    gemm_bf16<2><<<dim3(8, 32), 256, GEMM_SMEM_BYTES>>>(bproj, out);
}

// round 15
// speedup vs baseline: 1.3822x; 1.2489x over previous
#include <cuda_runtime.h>
#include <cuda_bf16.h>
#include <cuda_fp16.h>
#include <stdint.h>
#include <math.h>

#define BQ 2
#define TQ 2048
#define CQ 1024
#define HQ 16
#define DQ 64
#define BH (BQ*HQ)
#define M_ROWS 4096
#define K2 2048                 // doubled K for fp16 hi/lo A-split

// Scratch (allocation-free rule: static device globals)
__device__ float g_q[BQ*HQ*TQ*DQ];
__device__ float g_k[BQ*HQ*TQ*DQ];
__device__ float g_v[BQ*HQ*TQ*DQ];
__device__ __half g_qh[BQ*HQ*TQ*DQ];
__device__ __half g_kh[BQ*HQ*TQ*DQ];
__device__ __half g_vh[BQ*HQ*TQ*DQ];
__device__ __half g_A2[(long)M_ROWS * K2];     // [M][K2] = [ah | al]
__device__ __half g_B2[(long)K2 * 3072];       // qkv W: [bh ; bh] along K2
__device__ __half g_B2p[(long)K2 * 1024];      // proj W: [bh ; bh]

#define CP_ASYNC16(dst_u32, src_ptr) \
    asm volatile("cp.async.cg.shared.global [%0], [%1], 16;\n" \
                 :: "r"(dst_u32), "l"(src_ptr))
#define CP_COMMIT() asm volatile("cp.async.commit_group;\n")
#define CP_WAIT(n)  asm volatile("cp.async.wait_group %0;\n" :: "n"(n))

// ---------------------------------------------------------------------------
// fp32 -> fp16 conversions.
// A2 row m: [ah(0:1024) | al(1024:2048)], a = ah + al (11+11 bits, ~exact)
// B2: bh duplicated at rows k and 1024+k, so [ah|al]@[bh;bh] = a·bh.
// ---------------------------------------------------------------------------
__global__ void conv_A2(const float* __restrict__ src)
{
    int i = blockIdx.x * blockDim.x + threadIdx.x;
    if (i >= M_ROWS * CQ) return;
    int m = i >> 10, k = i & 1023;
    float v = src[i];
    __half hi = __float2half(v);
    __half lo = __float2half(v - __half2float(hi));
    long base = (long)m * K2;
    g_A2[base + k] = hi;
    g_A2[base + 1024 + k] = lo;
}

template<int WHICH>
__global__ void conv_B2(const float* __restrict__ W)
{
    const int N = WHICH ? 1024 : 3072;
    __half* dst = WHICH ? g_B2p : g_B2;
    int i = blockIdx.x * blockDim.x + threadIdx.x;
    if (i >= CQ * N) return;
    int k = i / N, n = i - k * N;
    __half bh = __float2half(W[i]);
    dst[(long)k * N + n] = bh;
    dst[(long)(1024 + k) * N + n] = bh;
}

// ---------------------------------------------------------------------------
// fp16 mma.sync GEMM, 2-stage cp.async, BK=32, STATIC smem (37.9 KB).
// Block tile 128x128, 256 threads = 8 warps (2m x 4n), warp tile 64x32.
// This is the R7-proven structure with __half types and K2=2048.
// MODE 1: B=g_B2, N=3072, scatter q/k/v; MODE 2: B=g_B2p, N=1024, write C.
// ---------------------------------------------------------------------------
template<int MODE>
__global__ __launch_bounds__(256)
void gemm_f16(const float* __restrict__ bias, float* __restrict__ C)
{
    const int N = (MODE == 1) ? 3072 : 1024;
    const __half* A = g_A2;
    const __half* B = (MODE == 1) ? g_B2 : g_B2p;

    __shared__ __half As[2][128][40];   // 80B row stride
    __shared__ __half Bs[2][32][136];   // 272B row stride

    int tid = threadIdx.x;
    int lane = tid & 31;
    int w = tid >> 5;
    int wm = (w & 1) * 64;
    int wn = (w >> 1) * 32;
    int m0 = blockIdx.y * 128;
    int n0 = blockIdx.x * 128;

    float acc[4][4][4];
    #pragma unroll
    for (int i = 0; i < 4; i++)
        #pragma unroll
        for (int j = 0; j < 4; j++)
            #pragma unroll
            for (int f = 0; f < 4; f++) acc[i][j][f] = 0.f;

    const int NIT = K2 / 32;   // 64

    // prefetch stage 0
    {
        #pragma unroll
        for (int p = 0; p < 2; p++) {
            int u = tid + p * 256;
            int ar = u >> 2, ac = (u & 3) * 8;
            uint32_t d = (uint32_t)__cvta_generic_to_shared(&As[0][ar][ac]);
            CP_ASYNC16(d, &A[(long)(m0 + ar) * K2 + ac]);
            int br = u >> 4, bc = (u & 15) * 8;
            uint32_t d2 = (uint32_t)__cvta_generic_to_shared(&Bs[0][br][bc]);
            CP_ASYNC16(d2, &B[(long)br * N + n0 + bc]);
        }
        CP_COMMIT();
    }

    for (int it = 0; it < NIT; it++) {
        int s = it & 1;
        if (it + 1 < NIT) {
            int k0 = (it + 1) * 32;
            int sn = s ^ 1;
            #pragma unroll
            for (int p = 0; p < 2; p++) {
                int u = tid + p * 256;
                int ar = u >> 2, ac = (u & 3) * 8;
                uint32_t d = (uint32_t)__cvta_generic_to_shared(&As[sn][ar][ac]);
                CP_ASYNC16(d, &A[(long)(m0 + ar) * K2 + k0 + ac]);
                int br = u >> 4, bc = (u & 15) * 8;
                uint32_t d2 = (uint32_t)__cvta_generic_to_shared(&Bs[sn][br][bc]);
                CP_ASYNC16(d2, &B[(long)(k0 + br) * N + n0 + bc]);
            }
            CP_COMMIT();
            CP_WAIT(1);
        } else {
            CP_WAIT(0);
        }
        __syncthreads();

        #pragma unroll
        for (int kk = 0; kk < 2; kk++) {
            int kb = kk * 16;
            uint32_t a[4][4], b[2][4];
            #pragma unroll
            for (int mi = 0; mi < 4; mi++) {
                uint32_t addr = (uint32_t)__cvta_generic_to_shared(
                    &As[s][wm + mi * 16 + (lane & 15)][kb + (lane >> 4) * 8]);
                asm volatile("ldmatrix.sync.aligned.m8n8.x4.shared.b16 {%0,%1,%2,%3},[%4];"
                             : "=r"(a[mi][0]), "=r"(a[mi][1]), "=r"(a[mi][2]), "=r"(a[mi][3])
                             : "r"(addr));
            }
            #pragma unroll
            for (int nj = 0; nj < 2; nj++) {
                uint32_t addr = (uint32_t)__cvta_generic_to_shared(
                    &Bs[s][kb + (lane & 15)][wn + nj * 16 + (lane >> 4) * 8]);
                asm volatile("ldmatrix.sync.aligned.m8n8.x4.trans.shared.b16 {%0,%1,%2,%3},[%4];"
                             : "=r"(b[nj][0]), "=r"(b[nj][1]), "=r"(b[nj][2]), "=r"(b[nj][3])
                             : "r"(addr));
            }
            #pragma unroll
            for (int mi = 0; mi < 4; mi++)
                #pragma unroll
                for (int ni = 0; ni < 4; ni++) {
                    uint32_t b0 = b[ni >> 1][(ni & 1) * 2 + 0];
                    uint32_t b1 = b[ni >> 1][(ni & 1) * 2 + 1];
                    float* d = acc[mi][ni];
                    asm volatile(
                        "mma.sync.aligned.m16n8k16.row.col.f32.f16.f16.f32 "
                        "{%0,%1,%2,%3},{%4,%5,%6,%7},{%8,%9},{%0,%1,%2,%3};"
                        : "+f"(d[0]), "+f"(d[1]), "+f"(d[2]), "+f"(d[3])
                        : "r"(a[mi][0]), "r"(a[mi][1]), "r"(a[mi][2]), "r"(a[mi][3]),
                          "r"(b0), "r"(b1));
                }
        }
        __syncthreads();
    }

    #pragma unroll
    for (int mi = 0; mi < 4; mi++)
        #pragma unroll
        for (int ni = 0; ni < 4; ni++)
            #pragma unroll
            for (int f = 0; f < 4; f++) {
                int m = m0 + wm + mi * 16 + (lane >> 2) + (f >> 1) * 8;
                int n = n0 + wn + ni * 8 + (lane & 3) * 2 + (f & 1);
                float v = acc[mi][ni][f] + bias[n];
                if (MODE == 1) {
                    int which = n >> 10;
                    int cc = n & 1023;
                    int h = cc >> 6;
                    int d = cc & 63;
                    int bb = m >> 11;
                    int t = m & 2047;
                    float* dst = (which == 0) ? g_q : ((which == 1) ? g_k : g_v);
                    dst[(((bb << 4) + h) * (long)TQ + t) * DQ + d] = v;
                } else {
                    C[(long)m * N + n] = v;
                }
            }
}

// ---------------------------------------------------------------------------
// RoPE: fp32 q/k -> fp16 q (pre-scaled 1/8), fp16 k, fp16 v (coalesced).
// ---------------------------------------------------------------------------
__global__ void rope_kernel()
{
    int idx = blockIdx.x * blockDim.x + threadIdx.x;
    int lane = idx & 31;
    int row = idx >> 5;
    if (row >= BH * TQ) return;
    int t = row & (TQ - 1);

    float inv_freq = 1.0f / powf(10000.0f, (float)(2 * lane) / 64.0f);
    float ang = (float)t * inv_freq;
    float c = cosf(ang);
    float s = sinf(ang);

    const float* qp = g_q + (long)row * DQ;
    float q0 = qp[lane], q1 = qp[lane + 32];
    g_qh[(long)row * DQ + lane]      = __float2half((q0 * c - q1 * s) * 0.125f);
    g_qh[(long)row * DQ + lane + 32] = __float2half((q1 * c + q0 * s) * 0.125f);

    const float* kp = g_k + (long)row * DQ;
    float k0 = kp[lane], k1 = kp[lane + 32];
    g_kh[(long)row * DQ + lane]      = __float2half(k0 * c - k1 * s);
    g_kh[(long)row * DQ + lane + 32] = __float2half(k1 * c + k0 * s);

    const float* vp = g_v + (long)row * DQ;
    g_vh[(long)row * DQ + lane]      = __float2half(vp[lane]);
    g_vh[(long)row * DQ + lane + 32] = __float2half(vp[lane + 32]);
}

// ---------------------------------------------------------------------------
// fp16 tensor-core flash attention; epilogue writes fp16 hi/lo A-split
// directly into g_A2 rows for the proj GEMM.
// ---------------------------------------------------------------------------
__global__ __launch_bounds__(128)
void flash_attn_h()
{
    __shared__ __half Qs[64][72];
    __shared__ __half Ks[64][72];
    __shared__ __half Vs[64][72];

    int bh = blockIdx.x;
    int y  = gridDim.y - 1 - blockIdx.y;
    int tid = threadIdx.x;
    int w = tid >> 5;
    int lane = tid & 31;

    const __half* qb = g_qh + (long)bh * TQ * DQ;
    const __half* kb = g_kh + (long)bh * TQ * DQ;
    const __half* vb = g_vh + (long)bh * TQ * DQ;

    #pragma unroll
    for (int p = 0; p < 4; p++) {
        int idx = tid + p * 128;
        int r = idx >> 3, c = (idx & 7) * 8;
        *(float4*)&Qs[r][c] = *(const float4*)&qb[(long)(y * 64 + r) * DQ + c];
    }
    __syncthreads();

    uint32_t qf[4][4];
    #pragma unroll
    for (int t = 0; t < 4; t++) {
        uint32_t addr = (uint32_t)__cvta_generic_to_shared(
            &Qs[w * 16 + (lane & 15)][t * 16 + (lane >> 4) * 8]);
        asm volatile("ldmatrix.sync.aligned.m8n8.x4.shared.b16 {%0,%1,%2,%3},[%4];"
                     : "=r"(qf[t][0]), "=r"(qf[t][1]), "=r"(qf[t][2]), "=r"(qf[t][3])
                     : "r"(addr));
    }

    float o[8][4];
    #pragma unroll
    for (int i = 0; i < 8; i++)
        #pragma unroll
        for (int f = 0; f < 4; f++) o[i][f] = 0.f;
    float m0 = -1e30f, m1 = -1e30f, l0 = 0.f, l1 = 0.f;

    for (int kc = 0; kc <= y; kc++) {
        __syncthreads();
        #pragma unroll
        for (int p = 0; p < 4; p++) {
            int idx = tid + p * 128;
            int r = idx >> 3, c = (idx & 7) * 8;
            *(float4*)&Ks[r][c] = *(const float4*)&kb[(long)(kc * 64 + r) * DQ + c];
            *(float4*)&Vs[r][c] = *(const float4*)&vb[(long)(kc * 64 + r) * DQ + c];
        }
        __syncthreads();

        float s[8][4];
        #pragma unroll
        for (int i = 0; i < 8; i++)
            #pragma unroll
            for (int f = 0; f < 4; f++) s[i][f] = 0.f;

        #pragma unroll
        for (int t = 0; t < 4; t++) {
            #pragma unroll
            for (int kj = 0; kj < 4; kj++) {
                uint32_t r[4];
                uint32_t addr = (uint32_t)__cvta_generic_to_shared(
                    &Ks[kj * 16 + (lane & 15)][t * 16 + (lane >> 4) * 8]);
                asm volatile("ldmatrix.sync.aligned.m8n8.x4.shared.b16 {%0,%1,%2,%3},[%4];"
                             : "=r"(r[0]), "=r"(r[1]), "=r"(r[2]), "=r"(r[3])
                             : "r"(addr));
                asm volatile(
                    "mma.sync.aligned.m16n8k16.row.col.f32.f16.f16.f32 "
                    "{%0,%1,%2,%3},{%4,%5,%6,%7},{%8,%9},{%0,%1,%2,%3};"
                    : "+f"(s[2*kj][0]), "+f"(s[2*kj][1]), "+f"(s[2*kj][2]), "+f"(s[2*kj][3])
                    : "r"(qf[t][0]), "r"(qf[t][1]), "r"(qf[t][2]), "r"(qf[t][3]),
                      "r"(r[0]), "r"(r[2]));
                asm volatile(
                    "mma.sync.aligned.m16n8k16.row.col.f32.f16.f16.f32 "
                    "{%0,%1,%2,%3},{%4,%5,%6,%7},{%8,%9},{%0,%1,%2,%3};"
                    : "+f"(s[2*kj+1][0]), "+f"(s[2*kj+1][1]), "+f"(s[2*kj+1][2]), "+f"(s[2*kj+1][3])
                    : "r"(qf[t][0]), "r"(qf[t][1]), "r"(qf[t][2]), "r"(qf[t][3]),
                      "r"(r[1]), "r"(r[3]));
            }
        }

        if (kc == y) {
            int qr0 = y * 64 + w * 16 + (lane >> 2);
            int qr1 = qr0 + 8;
            #pragma unroll
            for (int ni = 0; ni < 8; ni++) {
                int kcol = kc * 64 + ni * 8 + ((lane & 3) << 1);
                if (kcol     > qr0) s[ni][0] = -1e30f;
                if (kcol + 1 > qr0) s[ni][1] = -1e30f;
                if (kcol     > qr1) s[ni][2] = -1e30f;
                if (kcol + 1 > qr1) s[ni][3] = -1e30f;
            }
        }

        float mx0 = -1e30f, mx1 = -1e30f;
        #pragma unroll
        for (int ni = 0; ni < 8; ni++) {
            mx0 = fmaxf(mx0, fmaxf(s[ni][0], s[ni][1]));
            mx1 = fmaxf(mx1, fmaxf(s[ni][2], s[ni][3]));
        }
        mx0 = fmaxf(mx0, __shfl_xor_sync(0xffffffffu, mx0, 1));
        mx0 = fmaxf(mx0, __shfl_xor_sync(0xffffffffu, mx0, 2));
        mx1 = fmaxf(mx1, __shfl_xor_sync(0xffffffffu, mx1, 1));
        mx1 = fmaxf(mx1, __shfl_xor_sync(0xffffffffu, mx1, 2));
        float mn0 = fmaxf(m0, mx0), mn1 = fmaxf(m1, mx1);
        float a0 = __expf(m0 - mn0), a1 = __expf(m1 - mn1);
        m0 = mn0; m1 = mn1;

        float ls0 = 0.f, ls1 = 0.f;
        uint32_t pf01[8], pf23[8];
        #pragma unroll
        for (int ni = 0; ni < 8; ni++) {
            float p0 = __expf(s[ni][0] - mn0);
            float p1 = __expf(s[ni][1] - mn0);
            float p2 = __expf(s[ni][2] - mn1);
            float p3 = __expf(s[ni][3] - mn1);
            ls0 += p0 + p1;
            ls1 += p2 + p3;
            __half2 h01 = __floats2half2_rn(p0, p1);
            __half2 h23 = __floats2half2_rn(p2, p3);
            pf01[ni] = *(uint32_t*)&h01;
            pf23[ni] = *(uint32_t*)&h23;
        }
        l0 = l0 * a0 + ls0;
        l1 = l1 * a1 + ls1;
        #pragma unroll
        for (int ni = 0; ni < 8; ni++) {
            o[ni][0] *= a0; o[ni][1] *= a0;
            o[ni][2] *= a1; o[ni][3] *= a1;
        }

        #pragma unroll
        for (int t = 0; t < 4; t++) {
            uint32_t vf[4][4];
            #pragma unroll
            for (int dj = 0; dj < 4; dj++) {
                uint32_t addr = (uint32_t)__cvta_generic_to_shared(
                    &Vs[t * 16 + (lane & 15)][dj * 16 + (lane >> 4) * 8]);
                asm volatile("ldmatrix.sync.aligned.m8n8.x4.trans.shared.b16 {%0,%1,%2,%3},[%4];"
                             : "=r"(vf[dj][0]), "=r"(vf[dj][1]), "=r"(vf[dj][2]), "=r"(vf[dj][3])
                             : "r"(addr));
            }
            uint32_t pa0 = pf01[2 * t], pa1 = pf23[2 * t];
            uint32_t pa2 = pf01[2 * t + 1], pa3 = pf23[2 * t + 1];
            #pragma unroll
            for (int ni = 0; ni < 8; ni++) {
                uint32_t b0 = vf[ni >> 1][(ni & 1) * 2 + 0];
                uint32_t b1 = vf[ni >> 1][(ni & 1) * 2 + 1];
                asm volatile(
                    "mma.sync.aligned.m16n8k16.row.col.f32.f16.f16.f32 "
                    "{%0,%1,%2,%3},{%4,%5,%6,%7},{%8,%9},{%0,%1,%2,%3};"
                    : "+f"(o[ni][0]), "+f"(o[ni][1]), "+f"(o[ni][2]), "+f"(o[ni][3])
                    : "r"(pa0), "r"(pa1), "r"(pa2), "r"(pa3),
                      "r"(b0), "r"(b1));
            }
        }
    }

    l0 += __shfl_xor_sync(0xffffffffu, l0, 1);
    l0 += __shfl_xor_sync(0xffffffffu, l0, 2);
    l1 += __shfl_xor_sync(0xffffffffu, l1, 1);
    l1 += __shfl_xor_sync(0xffffffffu, l1, 2);
    float inv0 = 1.0f / l0, inv1 = 1.0f / l1;

    // fused epilogue: fp16 hi/lo A-split straight into g_A2
    int b = bh >> 4, h = bh & 15;
    int r0 = y * 64 + w * 16 + (lane >> 2);
    long mrow0 = (long)(b * TQ + r0) * K2;
    long mrow1 = (long)(b * TQ + r0 + 8) * K2;
    #pragma unroll
    for (int ni = 0; ni < 8; ni++) {
        int cc = h * 64 + ni * 8 + ((lane & 3) << 1);
        float v0x = o[ni][0] * inv0, v0y = o[ni][1] * inv0;
        float v1x = o[ni][2] * inv1, v1y = o[ni][3] * inv1;

        __half h0x = __float2half(v0x);
        __half h0y = __float2half(v0y);
        __half2 hi0; hi0.x = h0x; hi0.y = h0y;
        __half2 lo0;
        lo0.x = __float2half(v0x - __half2float(h0x));
        lo0.y = __float2half(v0y - __half2float(h0y));
        *(__half2*)&g_A2[mrow0 + cc]        = hi0;
        *(__half2*)&g_A2[mrow0 + 1024 + cc] = lo0;

        __half h1x = __float2half(v1x);
        __half h1y = __float2half(v1y);
        __half2 hi1; hi1.x = h1x; hi1.y = h1y;
        __half2 lo1;
        lo1.x = __float2half(v1x - __half2float(h1x));
        lo1.y = __float2half(v1y - __half2float(h1y));
        *(__half2*)&g_A2[mrow1 + cc]        = hi1;
        *(__half2*)&g_A2[mrow1 + 1024 + cc] = lo1;
    }
}

// ---------------------------------------------------------------------------
extern "C" void kernel_launch(void* const* d_in, const int* in_sizes, int n_in,
                              void* d_out, int out_size)
{
    const float* x     = (const float*)d_in[0];
    const float* Wqkv  = (const float*)d_in[1];
    const float* bqkv  = (const float*)d_in[2];
    const float* Wproj = (const float*)d_in[3];
    const float* bproj = (const float*)d_in[4];
    float* out = (float*)d_out;

    conv_A2<<<(M_ROWS * CQ) / 256, 256>>>(x);
    conv_B2<0><<<(CQ * 3072) / 256, 256>>>(Wqkv);
    conv_B2<1><<<(CQ * 1024) / 256, 256>>>(Wproj);
    gemm_f16<1><<<dim3(24, 32), 256>>>(bqkv, nullptr);

    rope_kernel<<<(BH * TQ * 32) / 256, 256>>>();
    flash_attn_h<<<dim3(BH, TQ / 64), 128>>>();   // writes g_A2 directly

    gemm_f16<2><<<dim3(8, 32), 256>>>(bproj, out);
}

// round 16
// speedup vs baseline: 1.9974x; 1.4451x over previous
#include <cuda_runtime.h>
#include <cuda_bf16.h>
#include <cuda_fp16.h>
#include <stdint.h>
#include <math.h>

#define BQ 2
#define TQ 2048
#define CQ 1024
#define HQ 16
#define DQ 64
#define BH (BQ*HQ)
#define M_ROWS 4096
#define KK 1024                 // plain fp16 GEMM K

// Scratch (allocation-free rule: static device globals)
__device__ float g_q[BQ*HQ*TQ*DQ];
__device__ float g_k[BQ*HQ*TQ*DQ];
__device__ float g_v[BQ*HQ*TQ*DQ];
__device__ __half g_qh[BQ*HQ*TQ*DQ];
__device__ __half g_kh[BQ*HQ*TQ*DQ];
__device__ __half g_vh[BQ*HQ*TQ*DQ];
__device__ __half g_A[(long)M_ROWS * KK];      // fp16 activations [M][K]
__device__ __half g_B[(long)KK * 3072];        // fp16 qkv weights [K][3072]
__device__ __half g_Bp[(long)KK * 1024];       // fp16 proj weights [K][1024]

#define CP_ASYNC16(dst_u32, src_ptr) \
    asm volatile("cp.async.cg.shared.global [%0], [%1], 16;\n" \
                 :: "r"(dst_u32), "l"(src_ptr))
#define CP_COMMIT() asm volatile("cp.async.commit_group;\n")
#define CP_WAIT(n)  asm volatile("cp.async.wait_group %0;\n" :: "n"(n))

// ---------------------------------------------------------------------------
// fp32 -> fp16 conversions (plain quantization).
// ---------------------------------------------------------------------------
__global__ void conv_A(const float* __restrict__ src)
{
    int i = blockIdx.x * blockDim.x + threadIdx.x;
    if (i >= M_ROWS * CQ) return;
    g_A[i] = __float2half(src[i]);
}

template<int WHICH>
__global__ void conv_B(const float* __restrict__ W)
{
    const int N = WHICH ? 1024 : 3072;
    __half* dst = WHICH ? g_Bp : g_B;
    int i = blockIdx.x * blockDim.x + threadIdx.x;
    if (i >= CQ * N) return;
    dst[i] = __float2half(W[i]);
}

// ---------------------------------------------------------------------------
// fp16 mma.sync GEMM, 2-stage cp.async, BK=32, static smem (R15 chassis).
// Block tile 128x128, 256 threads = 8 warps (2m x 4n), warp tile 64x32.
// MODE 1: B=g_B, N=3072, scatter q/k/v; MODE 2: B=g_Bp, N=1024, write C.
// ---------------------------------------------------------------------------
template<int MODE>
__global__ __launch_bounds__(256)
void gemm_f16(const float* __restrict__ bias, float* __restrict__ C)
{
    const int N = (MODE == 1) ? 3072 : 1024;
    const __half* A = g_A;
    const __half* B = (MODE == 1) ? g_B : g_Bp;

    __shared__ __half As[2][128][40];   // 80B row stride
    __shared__ __half Bs[2][32][136];   // 272B row stride

    int tid = threadIdx.x;
    int lane = tid & 31;
    int w = tid >> 5;
    int wm = (w & 1) * 64;
    int wn = (w >> 1) * 32;
    int m0 = blockIdx.y * 128;
    int n0 = blockIdx.x * 128;

    float acc[4][4][4];
    #pragma unroll
    for (int i = 0; i < 4; i++)
        #pragma unroll
        for (int j = 0; j < 4; j++)
            #pragma unroll
            for (int f = 0; f < 4; f++) acc[i][j][f] = 0.f;

    const int NIT = KK / 32;   // 32

    // prefetch stage 0
    {
        #pragma unroll
        for (int p = 0; p < 2; p++) {
            int u = tid + p * 256;
            int ar = u >> 2, ac = (u & 3) * 8;
            uint32_t d = (uint32_t)__cvta_generic_to_shared(&As[0][ar][ac]);
            CP_ASYNC16(d, &A[(long)(m0 + ar) * KK + ac]);
            int br = u >> 4, bc = (u & 15) * 8;
            uint32_t d2 = (uint32_t)__cvta_generic_to_shared(&Bs[0][br][bc]);
            CP_ASYNC16(d2, &B[(long)br * N + n0 + bc]);
        }
        CP_COMMIT();
    }

    for (int it = 0; it < NIT; it++) {
        int s = it & 1;
        if (it + 1 < NIT) {
            int k0 = (it + 1) * 32;
            int sn = s ^ 1;
            #pragma unroll
            for (int p = 0; p < 2; p++) {
                int u = tid + p * 256;
                int ar = u >> 2, ac = (u & 3) * 8;
                uint32_t d = (uint32_t)__cvta_generic_to_shared(&As[sn][ar][ac]);
                CP_ASYNC16(d, &A[(long)(m0 + ar) * KK + k0 + ac]);
                int br = u >> 4, bc = (u & 15) * 8;
                uint32_t d2 = (uint32_t)__cvta_generic_to_shared(&Bs[sn][br][bc]);
                CP_ASYNC16(d2, &B[(long)(k0 + br) * N + n0 + bc]);
            }
            CP_COMMIT();
            CP_WAIT(1);
        } else {
            CP_WAIT(0);
        }
        __syncthreads();

        #pragma unroll
        for (int kk = 0; kk < 2; kk++) {
            int kb = kk * 16;
            uint32_t a[4][4], b[2][4];
            #pragma unroll
            for (int mi = 0; mi < 4; mi++) {
                uint32_t addr = (uint32_t)__cvta_generic_to_shared(
                    &As[s][wm + mi * 16 + (lane & 15)][kb + (lane >> 4) * 8]);
                asm volatile("ldmatrix.sync.aligned.m8n8.x4.shared.b16 {%0,%1,%2,%3},[%4];"
                             : "=r"(a[mi][0]), "=r"(a[mi][1]), "=r"(a[mi][2]), "=r"(a[mi][3])
                             : "r"(addr));
            }
            #pragma unroll
            for (int nj = 0; nj < 2; nj++) {
                uint32_t addr = (uint32_t)__cvta_generic_to_shared(
                    &Bs[s][kb + (lane & 15)][wn + nj * 16 + (lane >> 4) * 8]);
                asm volatile("ldmatrix.sync.aligned.m8n8.x4.trans.shared.b16 {%0,%1,%2,%3},[%4];"
                             : "=r"(b[nj][0]), "=r"(b[nj][1]), "=r"(b[nj][2]), "=r"(b[nj][3])
                             : "r"(addr));
            }
            #pragma unroll
            for (int mi = 0; mi < 4; mi++)
                #pragma unroll
                for (int ni = 0; ni < 4; ni++) {
                    uint32_t b0 = b[ni >> 1][(ni & 1) * 2 + 0];
                    uint32_t b1 = b[ni >> 1][(ni & 1) * 2 + 1];
                    float* d = acc[mi][ni];
                    asm volatile(
                        "mma.sync.aligned.m16n8k16.row.col.f32.f16.f16.f32 "
                        "{%0,%1,%2,%3},{%4,%5,%6,%7},{%8,%9},{%0,%1,%2,%3};"
                        : "+f"(d[0]), "+f"(d[1]), "+f"(d[2]), "+f"(d[3])
                        : "r"(a[mi][0]), "r"(a[mi][1]), "r"(a[mi][2]), "r"(a[mi][3]),
                          "r"(b0), "r"(b1));
                }
        }
        __syncthreads();
    }

    #pragma unroll
    for (int mi = 0; mi < 4; mi++)
        #pragma unroll
        for (int ni = 0; ni < 4; ni++)
            #pragma unroll
            for (int f = 0; f < 4; f++) {
                int m = m0 + wm + mi * 16 + (lane >> 2) + (f >> 1) * 8;
                int n = n0 + wn + ni * 8 + (lane & 3) * 2 + (f & 1);
                float v = acc[mi][ni][f] + bias[n];
                if (MODE == 1) {
                    int which = n >> 10;
                    int cc = n & 1023;
                    int h = cc >> 6;
                    int d = cc & 63;
                    int bb = m >> 11;
                    int t = m & 2047;
                    float* dst = (which == 0) ? g_q : ((which == 1) ? g_k : g_v);
                    dst[(((bb << 4) + h) * (long)TQ + t) * DQ + d] = v;
                } else {
                    C[(long)m * N + n] = v;
                }
            }
}

// ---------------------------------------------------------------------------
// RoPE: fp32 q/k -> fp16 q (pre-scaled 1/8), fp16 k, fp16 v (coalesced).
// ---------------------------------------------------------------------------
__global__ void rope_kernel()
{
    int idx = blockIdx.x * blockDim.x + threadIdx.x;
    int lane = idx & 31;
    int row = idx >> 5;
    if (row >= BH * TQ) return;
    int t = row & (TQ - 1);

    float inv_freq = 1.0f / powf(10000.0f, (float)(2 * lane) / 64.0f);
    float ang = (float)t * inv_freq;
    float c = cosf(ang);
    float s = sinf(ang);

    const float* qp = g_q + (long)row * DQ;
    float q0 = qp[lane], q1 = qp[lane + 32];
    g_qh[(long)row * DQ + lane]      = __float2half((q0 * c - q1 * s) * 0.125f);
    g_qh[(long)row * DQ + lane + 32] = __float2half((q1 * c + q0 * s) * 0.125f);

    const float* kp = g_k + (long)row * DQ;
    float k0 = kp[lane], k1 = kp[lane + 32];
    g_kh[(long)row * DQ + lane]      = __float2half(k0 * c - k1 * s);
    g_kh[(long)row * DQ + lane + 32] = __float2half(k1 * c + k0 * s);

    const float* vp = g_v + (long)row * DQ;
    g_vh[(long)row * DQ + lane]      = __float2half(vp[lane]);
    g_vh[(long)row * DQ + lane + 32] = __float2half(vp[lane + 32]);
}

// ---------------------------------------------------------------------------
// fp16 tensor-core flash attention; epilogue writes fp16 y directly into
// g_A rows for the proj GEMM.
// ---------------------------------------------------------------------------
__global__ __launch_bounds__(128)
void flash_attn_h()
{
    __shared__ __half Qs[64][72];
    __shared__ __half Ks[64][72];
    __shared__ __half Vs[64][72];

    int bh = blockIdx.x;
    int y  = gridDim.y - 1 - blockIdx.y;
    int tid = threadIdx.x;
    int w = tid >> 5;
    int lane = tid & 31;

    const __half* qb = g_qh + (long)bh * TQ * DQ;
    const __half* kb = g_kh + (long)bh * TQ * DQ;
    const __half* vb = g_vh + (long)bh * TQ * DQ;

    #pragma unroll
    for (int p = 0; p < 4; p++) {
        int idx = tid + p * 128;
        int r = idx >> 3, c = (idx & 7) * 8;
        *(float4*)&Qs[r][c] = *(const float4*)&qb[(long)(y * 64 + r) * DQ + c];
    }
    __syncthreads();

    uint32_t qf[4][4];
    #pragma unroll
    for (int t = 0; t < 4; t++) {
        uint32_t addr = (uint32_t)__cvta_generic_to_shared(
            &Qs[w * 16 + (lane & 15)][t * 16 + (lane >> 4) * 8]);
        asm volatile("ldmatrix.sync.aligned.m8n8.x4.shared.b16 {%0,%1,%2,%3},[%4];"
                     : "=r"(qf[t][0]), "=r"(qf[t][1]), "=r"(qf[t][2]), "=r"(qf[t][3])
                     : "r"(addr));
    }

    float o[8][4];
    #pragma unroll
    for (int i = 0; i < 8; i++)
        #pragma unroll
        for (int f = 0; f < 4; f++) o[i][f] = 0.f;
    float m0 = -1e30f, m1 = -1e30f, l0 = 0.f, l1 = 0.f;

    for (int kc = 0; kc <= y; kc++) {
        __syncthreads();
        #pragma unroll
        for (int p = 0; p < 4; p++) {
            int idx = tid + p * 128;
            int r = idx >> 3, c = (idx & 7) * 8;
            *(float4*)&Ks[r][c] = *(const float4*)&kb[(long)(kc * 64 + r) * DQ + c];
            *(float4*)&Vs[r][c] = *(const float4*)&vb[(long)(kc * 64 + r) * DQ + c];
        }
        __syncthreads();

        float s[8][4];
        #pragma unroll
        for (int i = 0; i < 8; i++)
            #pragma unroll
            for (int f = 0; f < 4; f++) s[i][f] = 0.f;

        #pragma unroll
        for (int t = 0; t < 4; t++) {
            #pragma unroll
            for (int kj = 0; kj < 4; kj++) {
                uint32_t r[4];
                uint32_t addr = (uint32_t)__cvta_generic_to_shared(
                    &Ks[kj * 16 + (lane & 15)][t * 16 + (lane >> 4) * 8]);
                asm volatile("ldmatrix.sync.aligned.m8n8.x4.shared.b16 {%0,%1,%2,%3},[%4];"
                             : "=r"(r[0]), "=r"(r[1]), "=r"(r[2]), "=r"(r[3])
                             : "r"(addr));
                asm volatile(
                    "mma.sync.aligned.m16n8k16.row.col.f32.f16.f16.f32 "
                    "{%0,%1,%2,%3},{%4,%5,%6,%7},{%8,%9},{%0,%1,%2,%3};"
                    : "+f"(s[2*kj][0]), "+f"(s[2*kj][1]), "+f"(s[2*kj][2]), "+f"(s[2*kj][3])
                    : "r"(qf[t][0]), "r"(qf[t][1]), "r"(qf[t][2]), "r"(qf[t][3]),
                      "r"(r[0]), "r"(r[2]));
                asm volatile(
                    "mma.sync.aligned.m16n8k16.row.col.f32.f16.f16.f32 "
                    "{%0,%1,%2,%3},{%4,%5,%6,%7},{%8,%9},{%0,%1,%2,%3};"
                    : "+f"(s[2*kj+1][0]), "+f"(s[2*kj+1][1]), "+f"(s[2*kj+1][2]), "+f"(s[2*kj+1][3])
                    : "r"(qf[t][0]), "r"(qf[t][1]), "r"(qf[t][2]), "r"(qf[t][3]),
                      "r"(r[1]), "r"(r[3]));
            }
        }

        if (kc == y) {
            int qr0 = y * 64 + w * 16 + (lane >> 2);
            int qr1 = qr0 + 8;
            #pragma unroll
            for (int ni = 0; ni < 8; ni++) {
                int kcol = kc * 64 + ni * 8 + ((lane & 3) << 1);
                if (kcol     > qr0) s[ni][0] = -1e30f;
                if (kcol + 1 > qr0) s[ni][1] = -1e30f;
                if (kcol     > qr1) s[ni][2] = -1e30f;
                if (kcol + 1 > qr1) s[ni][3] = -1e30f;
            }
        }

        float mx0 = -1e30f, mx1 = -1e30f;
        #pragma unroll
        for (int ni = 0; ni < 8; ni++) {
            mx0 = fmaxf(mx0, fmaxf(s[ni][0], s[ni][1]));
            mx1 = fmaxf(mx1, fmaxf(s[ni][2], s[ni][3]));
        }
        mx0 = fmaxf(mx0, __shfl_xor_sync(0xffffffffu, mx0, 1));
        mx0 = fmaxf(mx0, __shfl_xor_sync(0xffffffffu, mx0, 2));
        mx1 = fmaxf(mx1, __shfl_xor_sync(0xffffffffu, mx1, 1));
        mx1 = fmaxf(mx1, __shfl_xor_sync(0xffffffffu, mx1, 2));
        float mn0 = fmaxf(m0, mx0), mn1 = fmaxf(m1, mx1);
        float a0 = __expf(m0 - mn0), a1 = __expf(m1 - mn1);
        m0 = mn0; m1 = mn1;

        float ls0 = 0.f, ls1 = 0.f;
        uint32_t pf01[8], pf23[8];
        #pragma unroll
        for (int ni = 0; ni < 8; ni++) {
            float p0 = __expf(s[ni][0] - mn0);
            float p1 = __expf(s[ni][1] - mn0);
            float p2 = __expf(s[ni][2] - mn1);
            float p3 = __expf(s[ni][3] - mn1);
            ls0 += p0 + p1;
            ls1 += p2 + p3;
            __half2 h01 = __floats2half2_rn(p0, p1);
            __half2 h23 = __floats2half2_rn(p2, p3);
            pf01[ni] = *(uint32_t*)&h01;
            pf23[ni] = *(uint32_t*)&h23;
        }
        l0 = l0 * a0 + ls0;
        l1 = l1 * a1 + ls1;
        #pragma unroll
        for (int ni = 0; ni < 8; ni++) {
            o[ni][0] *= a0; o[ni][1] *= a0;
            o[ni][2] *= a1; o[ni][3] *= a1;
        }

        #pragma unroll
        for (int t = 0; t < 4; t++) {
            uint32_t vf[4][4];
            #pragma unroll
            for (int dj = 0; dj < 4; dj++) {
                uint32_t addr = (uint32_t)__cvta_generic_to_shared(
                    &Vs[t * 16 + (lane & 15)][dj * 16 + (lane >> 4) * 8]);
                asm volatile("ldmatrix.sync.aligned.m8n8.x4.trans.shared.b16 {%0,%1,%2,%3},[%4];"
                             : "=r"(vf[dj][0]), "=r"(vf[dj][1]), "=r"(vf[dj][2]), "=r"(vf[dj][3])
                             : "r"(addr));
            }
            uint32_t pa0 = pf01[2 * t], pa1 = pf23[2 * t];
            uint32_t pa2 = pf01[2 * t + 1], pa3 = pf23[2 * t + 1];
            #pragma unroll
            for (int ni = 0; ni < 8; ni++) {
                uint32_t b0 = vf[ni >> 1][(ni & 1) * 2 + 0];
                uint32_t b1 = vf[ni >> 1][(ni & 1) * 2 + 1];
                asm volatile(
                    "mma.sync.aligned.m16n8k16.row.col.f32.f16.f16.f32 "
                    "{%0,%1,%2,%3},{%4,%5,%6,%7},{%8,%9},{%0,%1,%2,%3};"
                    : "+f"(o[ni][0]), "+f"(o[ni][1]), "+f"(o[ni][2]), "+f"(o[ni][3])
                    : "r"(pa0), "r"(pa1), "r"(pa2), "r"(pa3),
                      "r"(b0), "r"(b1));
            }
        }
    }

    l0 += __shfl_xor_sync(0xffffffffu, l0, 1);
    l0 += __shfl_xor_sync(0xffffffffu, l0, 2);
    l1 += __shfl_xor_sync(0xffffffffu, l1, 1);
    l1 += __shfl_xor_sync(0xffffffffu, l1, 2);
    float inv0 = 1.0f / l0, inv1 = 1.0f / l1;

    // fused epilogue: fp16 y straight into g_A rows
    int b = bh >> 4, h = bh & 15;
    int r0 = y * 64 + w * 16 + (lane >> 2);
    long mrow0 = (long)(b * TQ + r0) * KK;
    long mrow1 = (long)(b * TQ + r0 + 8) * KK;
    #pragma unroll
    for (int ni = 0; ni < 8; ni++) {
        int cc = h * 64 + ni * 8 + ((lane & 3) << 1);
        __half2 y0 = __floats2half2_rn(o[ni][0] * inv0, o[ni][1] * inv0);
        __half2 y1 = __floats2half2_rn(o[ni][2] * inv1, o[ni][3] * inv1);
        *(__half2*)&g_A[mrow0 + cc] = y0;
        *(__half2*)&g_A[mrow1 + cc] = y1;
    }
}

// ---------------------------------------------------------------------------
extern "C" void kernel_launch(void* const* d_in, const int* in_sizes, int n_in,
                              void* d_out, int out_size)
{
    const float* x     = (const float*)d_in[0];
    const float* Wqkv  = (const float*)d_in[1];
    const float* bqkv  = (const float*)d_in[2];
    const float* Wproj = (const float*)d_in[3];
    const float* bproj = (const float*)d_in[4];
    float* out = (float*)d_out;

    conv_A<<<(M_ROWS * CQ) / 256, 256>>>(x);
    conv_B<0><<<(CQ * 3072) / 256, 256>>>(Wqkv);
    conv_B<1><<<(CQ * 1024) / 256, 256>>>(Wproj);
    gemm_f16<1><<<dim3(24, 32), 256>>>(bqkv, nullptr);

    rope_kernel<<<(BH * TQ * 32) / 256, 256>>>();
    flash_attn_h<<<dim3(BH, TQ / 64), 128>>>();   // writes g_A directly

    gemm_f16<2><<<dim3(8, 32), 256>>>(bproj, out);
}